// round 8
// baseline (speedup 1.0000x reference)
#include <cuda_runtime.h>

// Problem constants (fixed by the reference)
#define BB 1024
#define NN 16
#define TT 256
#define TPB 64                      // 64 threads = 64 (b,t) pairs, 1 thread each
#define GRID (BB * (TT / TPB))      // 4096 blocks, 4 per batch b

#define TRI(i, j) ((i) * ((i) + 1) / 2 + (j))   // packed 4x4 lower-tri index

// Scratch for deterministic single-launch reduction (no cudaMalloc allowed)
__device__ float g_partials[GRID];
__device__ unsigned int g_count = 0;   // self-resetting arrival counter

// Factor a width-4 panel: T = 4x4 packed lower tri (diagonal block),
// R = NR x 4 rows below it. Fused forward solve on y[BASE..]. Pivots >= 1.
#define FACTOR_PANEL(T, R, NR, BASE)                                        \
    _Pragma("unroll")                                                       \
    for (int j = 0; j < 4; ++j) {                                           \
        const float s = T[TRI(j, j)];                                       \
        pivprod *= s;                                                       \
        const float invd = rsqrtf(s);                                       \
        y[BASE + j] *= invd;                                                \
        quad = fmaf(y[BASE + j], y[BASE + j], quad);                        \
        _Pragma("unroll")                                                   \
        for (int i = j + 1; i < 4; ++i) T[TRI(i, j)] *= invd;               \
        _Pragma("unroll")                                                   \
        for (int r = 0; r < NR; ++r) R[r][j] *= invd;                       \
        _Pragma("unroll")                                                   \
        for (int i = j + 1; i < 4; ++i)                                     \
            y[BASE + i] = fmaf(-T[TRI(i, j)], y[BASE + j], y[BASE + i]);    \
        _Pragma("unroll")                                                   \
        for (int r = 0; r < NR; ++r)                                        \
            y[BASE + 4 + r] = fmaf(-R[r][j], y[BASE + j], y[BASE + 4 + r]); \
        _Pragma("unroll")                                                   \
        for (int k = j + 1; k < 4; ++k) {                                   \
            const float ckj = T[TRI(k, j)];                                 \
            _Pragma("unroll")                                               \
            for (int i = k; i < 4; ++i)                                     \
                T[TRI(i, k)] = fmaf(-T[TRI(i, j)], ckj, T[TRI(i, k)]);      \
            _Pragma("unroll")                                               \
            for (int r = 0; r < NR; ++r)                                    \
                R[r][k] = fmaf(-R[r][j], ckj, R[r][k]);                     \
        }                                                                   \
    }

__global__ __launch_bounds__(TPB, 9) void gll_panel_kernel(
    const float* __restrict__ pred,
    const float* __restrict__ targ,
    const float* __restrict__ cov,
    float* __restrict__ out)
{
    const int tid = threadIdx.x;
    const int bid = blockIdx.x;
    const int b   = bid >> 2;
    const int t   = ((bid & 3) << 6) + tid;   // this thread's time index

    // cov plane (i,j) element t at cov[((b*16+i)*16+j)*256 + t]; consecutive
    // tid -> consecutive t -> fully coalesced 256B warp runs per plane.
    const float* covb = cov + ((size_t)b * NN * NN) * TT + t;

    float pivprod = 1.0f;
    float quad    = 0.0f;

    // ---- diff vector
    float y[NN];
#pragma unroll
    for (int i = 0; i < NN; ++i) {
        const int off = (b * NN + i) * TT + t;
        y[i] = pred[off] - targ[off];
    }

    // ================= Panel 1: cols 0-3 =================
    float T1[10];                 // rows 0-3, packed lower tri
    float R1[12][4];              // rows 4-15 x cols 0-3
#pragma unroll
    for (int i = 0; i < 4; ++i)
#pragma unroll
        for (int j = 0; j <= i; ++j)
            T1[TRI(i, j)] = covb[(i * NN + j) * TT];
#pragma unroll
    for (int r = 0; r < 12; ++r)
#pragma unroll
        for (int c = 0; c < 4; ++c)
            R1[r][c] = covb[((4 + r) * NN + c) * TT];

    FACTOR_PANEL(T1, R1, 12, 0)   // T1 dead after this

    // ================= Panel 2: cols 4-7 =================
    float T2[10];                 // rows 4-7 (local q), packed lower tri
    float R2[8][4];               // rows 8-15 (local r) x cols 4-7
#pragma unroll
    for (int q = 0; q < 4; ++q)
#pragma unroll
        for (int c = 0; c <= q; ++c)
            T2[TRI(q, c)] = covb[((4 + q) * NN + (4 + c)) * TT];
#pragma unroll
    for (int r = 0; r < 8; ++r)
#pragma unroll
        for (int c = 0; c < 4; ++c)
            R2[r][c] = covb[((8 + r) * NN + (4 + c)) * TT];

    // syrk update from panel 1 (L rows 4-15 live in R1)
#pragma unroll
    for (int c = 0; c < 4; ++c) {
#pragma unroll
        for (int m = 0; m < 4; ++m) {
            const float lcm = R1[c][m];                    // L[4+c][m]
#pragma unroll
            for (int q = c; q < 4; ++q)
                T2[TRI(q, c)] = fmaf(-R1[q][m], lcm, T2[TRI(q, c)]);
#pragma unroll
            for (int r = 0; r < 8; ++r)
                R2[r][c] = fmaf(-R1[r + 4][m], lcm, R2[r][c]);
        }
    }

    FACTOR_PANEL(T2, R2, 8, 4)    // R1 rows 0-3 dead after this

    // ================= Panel 3: cols 8-11 =================
    float T3[10];                 // rows 8-11, packed lower tri
    float R3[4][4];               // rows 12-15 x cols 8-11
#pragma unroll
    for (int q = 0; q < 4; ++q)
#pragma unroll
        for (int c = 0; c <= q; ++c)
            T3[TRI(q, c)] = covb[((8 + q) * NN + (8 + c)) * TT];
#pragma unroll
    for (int r = 0; r < 4; ++r)
#pragma unroll
        for (int c = 0; c < 4; ++c)
            R3[r][c] = covb[((12 + r) * NN + (8 + c)) * TT];

    // updates from panel 1 (R1 rows 4..11 ~ global 8-15) and panel 2 (R2)
#pragma unroll
    for (int c = 0; c < 4; ++c) {
#pragma unroll
        for (int m = 0; m < 4; ++m) {
            const float l1 = R1[c + 4][m];                 // L[8+c][m]
#pragma unroll
            for (int q = c; q < 4; ++q)
                T3[TRI(q, c)] = fmaf(-R1[q + 4][m], l1, T3[TRI(q, c)]);
#pragma unroll
            for (int r = 0; r < 4; ++r)
                R3[r][c] = fmaf(-R1[r + 8][m], l1, R3[r][c]);

            const float l2 = R2[c][m];                     // L[8+c][4+m]
#pragma unroll
            for (int q = c; q < 4; ++q)
                T3[TRI(q, c)] = fmaf(-R2[q][m], l2, T3[TRI(q, c)]);
#pragma unroll
            for (int r = 0; r < 4; ++r)
                R3[r][c] = fmaf(-R2[r + 4][m], l2, R3[r][c]);
        }
    }

    FACTOR_PANEL(T3, R3, 4, 8)    // R1 rows 4-7, R2 rows 0-3 dead after this

    // ================= Panel 4: cols 12-15 =================
    float T4[10];                 // rows 12-15, packed lower tri
#pragma unroll
    for (int q = 0; q < 4; ++q)
#pragma unroll
        for (int c = 0; c <= q; ++c)
            T4[TRI(q, c)] = covb[((12 + q) * NN + (12 + c)) * TT];

    // updates from panels 1-3 (rows 12-15: R1[8..11], R2[4..7], R3[0..3])
#pragma unroll
    for (int c = 0; c < 4; ++c) {
#pragma unroll
        for (int m = 0; m < 4; ++m) {
            const float l1 = R1[c + 8][m];
#pragma unroll
            for (int q = c; q < 4; ++q)
                T4[TRI(q, c)] = fmaf(-R1[q + 8][m], l1, T4[TRI(q, c)]);
            const float l2 = R2[c + 4][m];
#pragma unroll
            for (int q = c; q < 4; ++q)
                T4[TRI(q, c)] = fmaf(-R2[q + 4][m], l2, T4[TRI(q, c)]);
            const float l3 = R3[c][m];
#pragma unroll
            for (int q = c; q < 4; ++q)
                T4[TRI(q, c)] = fmaf(-R3[q][m], l3, T4[TRI(q, c)]);
        }
    }

    FACTOR_PANEL(T4, R3 /*dummy, NR=0*/, 0, 12)

    // pivprod = det(Sigma) >= 1, well within fp32 range -> one __logf.
    float v = quad + __logf(pivprod);

    // ---- In-block reduction: warp shuffles + 2-warp smem combine
    const int lane = tid & 31;
    const int wid  = tid >> 5;
#pragma unroll
    for (int o = 16; o > 0; o >>= 1) v += __shfl_down_sync(0xffffffffu, v, o);

    __shared__ float warpsum[TPB / 32];
    __shared__ bool  isLast;
    if (lane == 0) warpsum[wid] = v;
    __syncthreads();

    if (tid == 0) {
        float s = warpsum[0] + warpsum[1];
        g_partials[bid] = s;
        __threadfence();
        unsigned int c = atomicAdd(&g_count, 1u);
        isLast = (c == (unsigned int)(GRID - 1));
    }
    __syncthreads();

    // Last arriving block performs the deterministic final sum (fixed order).
    if (isLast) {
        float s = 0.0f;
#pragma unroll 8
        for (int i = tid; i < GRID; i += TPB) s += g_partials[i];
#pragma unroll
        for (int o = 16; o > 0; o >>= 1) s += __shfl_down_sync(0xffffffffu, s, o);
        if (lane == 0) warpsum[wid] = s;
        __syncthreads();
        if (tid == 0) {
            out[0] = (warpsum[0] + warpsum[1]) * (1.0f / (float)(BB * TT));
            g_count = 0;   // reset for the next graph replay
        }
    }
}

extern "C" void kernel_launch(void* const* d_in, const int* in_sizes, int n_in,
                              void* d_out, int out_size)
{
    const float* pred = (const float*)d_in[0];   // prediction [B,N,T]
    const float* targ = (const float*)d_in[1];   // target     [B,N,T]
    const float* cov  = (const float*)d_in[2];   // cov        [B,N,N,T]
    float* out = (float*)d_out;

    gll_panel_kernel<<<GRID, TPB>>>(pred, targ, cov, out);
}

// round 10
// speedup vs baseline: 1.0769x; 1.0769x over previous
#include <cuda_runtime.h>

// Problem constants (fixed by the reference)
#define BB 1024
#define NN 16
#define TT 256
#define TPB 64                      // 64 threads = 64 (b,t) pairs, 1 thread each
#define GRID (BB * (TT / TPB))      // 4096 blocks, 4 per batch b

#define TRI(i, j) ((i) * ((i) + 1) / 2 + (j))   // packed 4x4 lower-tri index

// Scratch for deterministic single-launch reduction (no cudaMalloc allowed)
__device__ float g_partials[GRID];
__device__ unsigned int g_count = 0;   // self-resetting arrival counter

// Factor a width-4 panel: T = 4x4 packed lower tri (diagonal block),
// R = NR x 4 rows below it. Fused forward solve on y[BASE..]. Pivots >= 1.
#define FACTOR_PANEL(T, R, NR, BASE)                                        \
    _Pragma("unroll")                                                       \
    for (int j = 0; j < 4; ++j) {                                           \
        const float s = T[TRI(j, j)];                                       \
        pivprod *= s;                                                       \
        const float invd = rsqrtf(s);                                       \
        y[BASE + j] *= invd;                                                \
        quad = fmaf(y[BASE + j], y[BASE + j], quad);                        \
        _Pragma("unroll")                                                   \
        for (int i = j + 1; i < 4; ++i) T[TRI(i, j)] *= invd;               \
        _Pragma("unroll")                                                   \
        for (int r = 0; r < NR; ++r) R[r][j] *= invd;                       \
        _Pragma("unroll")                                                   \
        for (int i = j + 1; i < 4; ++i)                                     \
            y[BASE + i] = fmaf(-T[TRI(i, j)], y[BASE + j], y[BASE + i]);    \
        _Pragma("unroll")                                                   \
        for (int r = 0; r < NR; ++r)                                        \
            y[BASE + 4 + r] = fmaf(-R[r][j], y[BASE + j], y[BASE + 4 + r]); \
        _Pragma("unroll")                                                   \
        for (int k = j + 1; k < 4; ++k) {                                   \
            const float ckj = T[TRI(k, j)];                                 \
            _Pragma("unroll")                                               \
            for (int i = k; i < 4; ++i)                                     \
                T[TRI(i, k)] = fmaf(-T[TRI(i, j)], ckj, T[TRI(i, k)]);      \
            _Pragma("unroll")                                               \
            for (int r = 0; r < NR; ++r)                                    \
                R[r][k] = fmaf(-R[r][j], ckj, R[r][k]);                     \
        }                                                                   \
    }

__global__ __launch_bounds__(TPB, 7) void gll_prefetch_kernel(
    const float* __restrict__ pred,
    const float* __restrict__ targ,
    const float* __restrict__ cov,
    float* __restrict__ out)
{
    const int tid = threadIdx.x;
    const int bid = blockIdx.x;
    const int b   = bid >> 2;
    const int t   = ((bid & 3) << 6) + tid;   // this thread's time index

    // cov plane (i,j) element t at cov[((b*16+i)*16+j)*256 + t]; consecutive
    // tid -> consecutive t -> fully coalesced 256B warp runs per plane.
    const float* covb = cov + ((size_t)b * NN * NN) * TT + t;

    float pivprod = 1.0f;
    float quad    = 0.0f;

    // ======== Stage 0: issue loads for y, panel 1 AND panel 2 up front ====
    float y[NN];
#pragma unroll
    for (int i = 0; i < NN; ++i) {
        const int off = (b * NN + i) * TT + t;
        y[i] = pred[off] - targ[off];
    }

    float T1[10];                 // rows 0-3, packed lower tri
    float R1[12][4];              // rows 4-15 x cols 0-3
#pragma unroll
    for (int i = 0; i < 4; ++i)
#pragma unroll
        for (int j = 0; j <= i; ++j)
            T1[TRI(i, j)] = covb[(i * NN + j) * TT];
#pragma unroll
    for (int r = 0; r < 12; ++r)
#pragma unroll
        for (int c = 0; c < 4; ++c)
            R1[r][c] = covb[((4 + r) * NN + c) * TT];

    // Prefetch panel 2 NOW: its DRAM latency hides under panel-1 compute.
    float T2[10];                 // rows 4-7 (local), packed lower tri
    float R2[8][4];               // rows 8-15 x cols 4-7
#pragma unroll
    for (int q = 0; q < 4; ++q)
#pragma unroll
        for (int c = 0; c <= q; ++c)
            T2[TRI(q, c)] = covb[((4 + q) * NN + (4 + c)) * TT];
#pragma unroll
    for (int r = 0; r < 8; ++r)
#pragma unroll
        for (int c = 0; c < 4; ++c)
            R2[r][c] = covb[((8 + r) * NN + (4 + c)) * TT];

    // ======== Compute panel 1 (overlaps panel-2 loads) ========
    FACTOR_PANEL(T1, R1, 12, 0)   // T1 dead after this

    // Prefetch panel 3: hides under panel-2 syrk + factor.
    float T3[10];                 // rows 8-11, packed lower tri
    float R3[4][4];               // rows 12-15 x cols 8-11
#pragma unroll
    for (int q = 0; q < 4; ++q)
#pragma unroll
        for (int c = 0; c <= q; ++c)
            T3[TRI(q, c)] = covb[((8 + q) * NN + (8 + c)) * TT];
#pragma unroll
    for (int r = 0; r < 4; ++r)
#pragma unroll
        for (int c = 0; c < 4; ++c)
            R3[r][c] = covb[((12 + r) * NN + (8 + c)) * TT];

    // ======== Panel 2: syrk from panel 1, then factor ========
#pragma unroll
    for (int c = 0; c < 4; ++c) {
#pragma unroll
        for (int m = 0; m < 4; ++m) {
            const float lcm = R1[c][m];                    // L[4+c][m]
#pragma unroll
            for (int q = c; q < 4; ++q)
                T2[TRI(q, c)] = fmaf(-R1[q][m], lcm, T2[TRI(q, c)]);
#pragma unroll
            for (int r = 0; r < 8; ++r)
                R2[r][c] = fmaf(-R1[r + 4][m], lcm, R2[r][c]);
        }
    }
    FACTOR_PANEL(T2, R2, 8, 4)

    // Prefetch panel 4: hides under panel-3 updates + factor.
    float T4[10];                 // rows 12-15, packed lower tri
#pragma unroll
    for (int q = 0; q < 4; ++q)
#pragma unroll
        for (int c = 0; c <= q; ++c)
            T4[TRI(q, c)] = covb[((12 + q) * NN + (12 + c)) * TT];

    // ======== Panel 3: updates from panels 1-2, then factor ========
#pragma unroll
    for (int c = 0; c < 4; ++c) {
#pragma unroll
        for (int m = 0; m < 4; ++m) {
            const float l1 = R1[c + 4][m];                 // L[8+c][m]
#pragma unroll
            for (int q = c; q < 4; ++q)
                T3[TRI(q, c)] = fmaf(-R1[q + 4][m], l1, T3[TRI(q, c)]);
#pragma unroll
            for (int r = 0; r < 4; ++r)
                R3[r][c] = fmaf(-R1[r + 8][m], l1, R3[r][c]);

            const float l2 = R2[c][m];                     // L[8+c][4+m]
#pragma unroll
            for (int q = c; q < 4; ++q)
                T3[TRI(q, c)] = fmaf(-R2[q][m], l2, T3[TRI(q, c)]);
#pragma unroll
            for (int r = 0; r < 4; ++r)
                R3[r][c] = fmaf(-R2[r + 4][m], l2, R3[r][c]);
        }
    }
    FACTOR_PANEL(T3, R3, 4, 8)

    // ======== Panel 4: updates from panels 1-3, then factor ========
#pragma unroll
    for (int c = 0; c < 4; ++c) {
#pragma unroll
        for (int m = 0; m < 4; ++m) {
            const float l1 = R1[c + 8][m];
#pragma unroll
            for (int q = c; q < 4; ++q)
                T4[TRI(q, c)] = fmaf(-R1[q + 8][m], l1, T4[TRI(q, c)]);
            const float l2 = R2[c + 4][m];
#pragma unroll
            for (int q = c; q < 4; ++q)
                T4[TRI(q, c)] = fmaf(-R2[q + 4][m], l2, T4[TRI(q, c)]);
            const float l3 = R3[c][m];
#pragma unroll
            for (int q = c; q < 4; ++q)
                T4[TRI(q, c)] = fmaf(-R3[q][m], l3, T4[TRI(q, c)]);
        }
    }
    FACTOR_PANEL(T4, R3 /*dummy, NR=0*/, 0, 12)

    // pivprod = det(Sigma) >= 1, well within fp32 range -> one __logf.
    float v = quad + __logf(pivprod);

    // ---- In-block reduction: warp shuffles + 2-warp smem combine
    const int lane = tid & 31;
    const int wid  = tid >> 5;
#pragma unroll
    for (int o = 16; o > 0; o >>= 1) v += __shfl_down_sync(0xffffffffu, v, o);

    __shared__ float warpsum[TPB / 32];
    __shared__ bool  isLast;
    if (lane == 0) warpsum[wid] = v;
    __syncthreads();

    if (tid == 0) {
        float s = warpsum[0] + warpsum[1];
        g_partials[bid] = s;
        __threadfence();
        unsigned int c = atomicAdd(&g_count, 1u);
        isLast = (c == (unsigned int)(GRID - 1));
    }
    __syncthreads();

    // Last arriving block performs the deterministic final sum (fixed order).
    if (isLast) {
        float s = 0.0f;
#pragma unroll 8
        for (int i = tid; i < GRID; i += TPB) s += g_partials[i];
#pragma unroll
        for (int o = 16; o > 0; o >>= 1) s += __shfl_down_sync(0xffffffffu, s, o);
        if (lane == 0) warpsum[wid] = s;
        __syncthreads();
        if (tid == 0) {
            out[0] = (warpsum[0] + warpsum[1]) * (1.0f / (float)(BB * TT));
            g_count = 0;   // reset for the next graph replay
        }
    }
}

extern "C" void kernel_launch(void* const* d_in, const int* in_sizes, int n_in,
                              void* d_out, int out_size)
{
    const float* pred = (const float*)d_in[0];   // prediction [B,N,T]
    const float* targ = (const float*)d_in[1];   // target     [B,N,T]
    const float* cov  = (const float*)d_in[2];   // cov        [B,N,N,T]
    float* out = (float*)d_out;

    gll_prefetch_kernel<<<GRID, TPB>>>(pred, targ, cov, out);
}